// round 2
// baseline (speedup 1.0000x reference)
#include <cuda_runtime.h>
#include <math.h>

#define BATCH   2
#define SEQLEN  2048
#define DMODEL  512
#define DSTATE  64
#define NCHUNK  4
#define LCHUNK  (SEQLEN / NCHUNK)   // 512
#define TILE    32
#define NTILES  (LCHUNK / TILE)     // 16

// end-of-chunk local states: [b][h][k][n]
__device__ float g_zend[BATCH * DMODEL * NCHUNK * DSTATE];

__device__ __forceinline__ void coeffs(int h, int n0, int n1,
                                       const float* __restrict__ log_dt,
                                       const float* __restrict__ B_re,
                                       const float* __restrict__ C_re,
                                       float& a0, float& a1, float& c0, float& c1,
                                       float& dA0, float& dA1, float& delta)
{
    delta = expf(log_dt[h]);
    const float A0 = rsqrtf(1.0f + (float)(n0 + 1) * (1.0f / DSTATE));
    const float A1 = rsqrtf(1.0f + (float)(n1 + 1) * (1.0f / DSTATE));
    dA0 = delta * A0;
    dA1 = delta * A1;
    a0 = expf(dA0);
    a1 = expf(dA1);
    c0 = expm1f(dA0) * B_re[n0] * delta * C_re[n0];
    c1 = expm1f(dA1) * B_re[n1] * delta * C_re[n1];
}

// Butterfly transpose-reduction: on entry p[s] = this lane's contribution to
// timestep t0+s; on exit p[0] = full 32-lane sum for timestep t0+lane.
__device__ __forceinline__ void tree_reduce(float* p, int lane)
{
#pragma unroll
    for (int m = 16; m >= 1; m >>= 1) {
#pragma unroll
        for (int j = 0; j < m; ++j) {
            const bool hi = (lane & m) != 0;
            const float mine = hi ? p[m + j] : p[j];
            const float oth  = hi ? p[j]     : p[m + j];
            p[j] = mine + __shfl_xor_sync(0xffffffffu, oth, m);
        }
    }
}

// Phase 1: per-(b,h,chunk) local scan with zero initial state.
__global__ __launch_bounds__(128, 8)
void s4_chunk_scan(const float* __restrict__ u,
                   const float* __restrict__ B_re,
                   const float* __restrict__ C_re,
                   const float* __restrict__ log_dt,
                   const float* __restrict__ Dp,
                   float* __restrict__ y)
{
    const int warp = blockIdx.x * (blockDim.x >> 5) + (threadIdx.x >> 5);
    const int lane = threadIdx.x & 31;
    const int k = warp & (NCHUNK - 1);
    const int h = (warp >> 2) & (DMODEL - 1);
    const int b = warp >> 11;

    const int n0 = lane * 2, n1 = n0 + 1;
    float a0, a1, c0, c1, dA0, dA1, delta;
    coeffs(h, n0, n1, log_dt, B_re, C_re, a0, a1, c0, c1, dA0, dA1, delta);
    const float Dh = Dp[h];

    const size_t base = ((size_t)b * SEQLEN + (size_t)k * LCHUNK) * DMODEL + h;
    const float* ub = u + base;
    float*       yb = y + base;

    float z0 = 0.0f, z1 = 0.0f;
    float ucur = ub[(size_t)lane * DMODEL];

    for (int tile = 0; tile < NTILES; ++tile) {
        const int t0 = tile * TILE;
        float unext = 0.0f;
        if (tile + 1 < NTILES)
            unext = ub[(size_t)(t0 + TILE + lane) * DMODEL];

        float p[TILE];
#pragma unroll
        for (int s = 0; s < TILE; ++s) {
            const float ut = __shfl_sync(0xffffffffu, ucur, s);
            z0 = fmaf(a0, z0, ut);
            z1 = fmaf(a1, z1, ut);
            p[s] = fmaf(c1, z1, c0 * z0);
        }

        tree_reduce(p, lane);

        yb[(size_t)(t0 + lane) * DMODEL] = p[0] + Dh * ucur;
        ucur = unext;
    }

    // store end-of-chunk local state
    float2* zout = (float2*)&g_zend[(((size_t)b * DMODEL + h) * NCHUNK + k) * DSTATE + n0];
    *zout = make_float2(z0, z1);
}

// Phase 2: for chunk k>=1, add carry correction: y(t0+tau) += sum_n c_n a_n^{tau+1} S_n
// where S = sum_{j<k} q^{k-1-j} z_end_j, q = a^LCHUNK.
__global__ __launch_bounds__(128, 8)
void s4_chunk_fix(const float* __restrict__ B_re,
                  const float* __restrict__ C_re,
                  const float* __restrict__ log_dt,
                  float* __restrict__ y)
{
    const int warp = blockIdx.x * (blockDim.x >> 5) + (threadIdx.x >> 5);
    const int lane = threadIdx.x & 31;
    const int k = 1 + (warp % (NCHUNK - 1));
    const int h = (warp / (NCHUNK - 1)) & (DMODEL - 1);
    const int b = warp / ((NCHUNK - 1) * DMODEL);

    const int n0 = lane * 2, n1 = n0 + 1;
    float a0, a1, c0, c1, dA0, dA1, delta;
    coeffs(h, n0, n1, log_dt, B_re, C_re, a0, a1, c0, c1, dA0, dA1, delta);
    const float q0 = expf(dA0 * (float)LCHUNK);
    const float q1 = expf(dA1 * (float)LCHUNK);

    // carry state entering chunk k
    float S0 = 0.0f, S1 = 0.0f;
    const float2* zl = (const float2*)&g_zend[(((size_t)b * DMODEL + h) * NCHUNK) * DSTATE + n0];
    for (int j = 0; j < k; ++j) {
        const float2 zj = zl[(size_t)j * (DSTATE / 2) * 2 / 2 * 0 + (size_t)j * (DSTATE / 2)];
        S0 = fmaf(q0, S0, zj.x);
        S1 = fmaf(q1, S1, zj.y);
    }

    float g0 = a0 * S0;   // correction state at tau=0 is a*S
    float g1 = a1 * S1;

    float* yb = y + ((size_t)b * SEQLEN + (size_t)k * LCHUNK) * DMODEL + h;

    for (int tile = 0; tile < NTILES; ++tile) {
        const int t0 = tile * TILE;
        const float yv = yb[(size_t)(t0 + lane) * DMODEL];   // prefetch RMW load

        float p[TILE];
#pragma unroll
        for (int s = 0; s < TILE; ++s) {
            p[s] = fmaf(c1, g1, c0 * g0);
            g0 *= a0;
            g1 *= a1;
        }

        tree_reduce(p, lane);

        yb[(size_t)(t0 + lane) * DMODEL] = yv + p[0];
    }
}

extern "C" void kernel_launch(void* const* d_in, const int* in_sizes, int n_in,
                              void* d_out, int out_size)
{
    const float* u      = (const float*)d_in[0];
    const float* B_re   = (const float*)d_in[1];
    const float* C_re   = (const float*)d_in[2];
    const float* log_dt = (const float*)d_in[3];
    const float* Dp     = (const float*)d_in[4];
    float* y = (float*)d_out;

    // Phase 1: BATCH*DMODEL*NCHUNK = 4096 warps, 4 warps/block
    s4_chunk_scan<<<(BATCH * DMODEL * NCHUNK) / 4, 128>>>(u, B_re, C_re, log_dt, Dp, y);
    // Phase 2: BATCH*DMODEL*(NCHUNK-1) = 3072 warps
    s4_chunk_fix<<<(BATCH * DMODEL * (NCHUNK - 1)) / 4, 128>>>(B_re, C_re, log_dt, y);
}

// round 3
// speedup vs baseline: 2.1824x; 2.1824x over previous
#include <cuda_runtime.h>
#include <math.h>

#define BATCH  2
#define SEQLEN 2048
#define H      512
#define NST    64
#define NP     32          // state pairs per channel
#define K      32          // time chunks
#define TCH    64          // SEQLEN / K

typedef unsigned long long u64;

// coefficient tables, pair-packed, [pair j][h] layout (coalesced over h)
__device__ u64 g_a2[NP * H];
__device__ u64 g_c2[NP * H];
__device__ u64 g_q2[NP * H];
// end-of-chunk local states and chunk-entry carries: [b][k][j][h]
__device__ u64 g_zend[BATCH * K * NP * H];
__device__ u64 g_S[BATCH * K * NP * H];

__device__ __forceinline__ u64 pack2(float lo, float hi) {
    u64 r; asm("mov.b64 %0, {%1, %2};" : "=l"(r) : "f"(lo), "f"(hi)); return r;
}
__device__ __forceinline__ void unpack2(u64 v, float& lo, float& hi) {
    asm("mov.b64 {%0, %1}, %2;" : "=f"(lo), "=f"(hi) : "l"(v));
}
__device__ __forceinline__ u64 fma2_(u64 a, u64 b, u64 c) {
    u64 d; asm("fma.rn.f32x2 %0, %1, %2, %3;" : "=l"(d) : "l"(a), "l"(b), "l"(c)); return d;
}
__device__ __forceinline__ u64 mul2_(u64 a, u64 b) {
    u64 d; asm("mul.rn.f32x2 %0, %1, %2;" : "=l"(d) : "l"(a), "l"(b)); return d;
}
__device__ __forceinline__ u64 add2_(u64 a, u64 b) {
    u64 d; asm("add.rn.f32x2 %0, %1, %2;" : "=l"(d) : "l"(a), "l"(b)); return d;
}

// ---------------------------------------------------------------- precompute
__global__ void s4_precomp(const float* __restrict__ B_re,
                           const float* __restrict__ C_re,
                           const float* __restrict__ log_dt)
{
    const int idx = blockIdx.x * blockDim.x + threadIdx.x;   // (j, h)
    if (idx >= NP * H) return;
    const int h = idx % H;
    const int j = idx / H;
    const float delta = expf(log_dt[h]);
    float av[2], cv[2], qv[2];
#pragma unroll
    for (int s = 0; s < 2; ++s) {
        const int n = 2 * j + s;
        const float A  = rsqrtf(1.0f + (float)(n + 1) * (1.0f / NST));
        const float dA = delta * A;
        av[s] = expf(dA);
        cv[s] = expm1f(dA) * B_re[n] * delta * C_re[n];
        qv[s] = expf(dA * (float)TCH);
    }
    g_a2[idx] = pack2(av[0], av[1]);
    g_c2[idx] = pack2(cv[0], cv[1]);
    g_q2[idx] = pack2(qv[0], qv[1]);
}

// ------------------------------------------------------------------ scan
// warp = (b, hw, k); lane = h_local. Each lane owns all 64 states of its h.
__global__ __launch_bounds__(128, 2)
void s4_scan(const float* __restrict__ u,
             const float* __restrict__ Dp,
             float* __restrict__ y)
{
    const int warp = blockIdx.x * 4 + (threadIdx.x >> 5);
    const int lane = threadIdx.x & 31;
    const int k  = warp & (K - 1);
    const int hw = (warp >> 5) & 15;
    const int b  = warp >> 9;
    const int h  = hw * 32 + lane;

    u64 a[NP], c[NP], z[NP];
#pragma unroll
    for (int j = 0; j < NP; ++j) {
        a[j] = g_a2[j * H + h];
        c[j] = g_c2[j * H + h];
        z[j] = 0ull;                 // (+0, +0)
    }
    const float Dh = Dp[h];

    const size_t base = ((size_t)b * SEQLEN + (size_t)k * TCH) * H + h;
    const float* ub = u + base;
    float*       yb = y + base;

    float up0 = ub[0 * H], up1 = ub[1 * H], up2 = ub[2 * H], up3 = ub[3 * H];

    for (int t = 0; t < TCH; t += 4) {
        float uc[4] = {up0, up1, up2, up3};
        if (t + 4 < TCH) {
            const float* p = ub + (size_t)(t + 4) * H;
            up0 = p[0 * H]; up1 = p[1 * H]; up2 = p[2 * H]; up3 = p[3 * H];
        }
#pragma unroll
        for (int s = 0; s < 4; ++s) {
            const float ut = uc[s];
            const u64 ubb = pack2(ut, ut);
            u64 ac0 = 0ull, ac1 = 0ull, ac2 = 0ull, ac3 = 0ull;
#pragma unroll
            for (int j = 0; j < NP; j += 4) {
                z[j + 0] = fma2_(a[j + 0], z[j + 0], ubb); ac0 = fma2_(c[j + 0], z[j + 0], ac0);
                z[j + 1] = fma2_(a[j + 1], z[j + 1], ubb); ac1 = fma2_(c[j + 1], z[j + 1], ac1);
                z[j + 2] = fma2_(a[j + 2], z[j + 2], ubb); ac2 = fma2_(c[j + 2], z[j + 2], ac2);
                z[j + 3] = fma2_(a[j + 3], z[j + 3], ubb); ac3 = fma2_(c[j + 3], z[j + 3], ac3);
            }
            const u64 sA = add2_(ac0, ac1);
            const u64 sB = add2_(ac2, ac3);
            const u64 sS = add2_(sA, sB);
            float x0, x1; unpack2(sS, x0, x1);
            yb[(size_t)(t + s) * H] = fmaf(Dh, ut, x0 + x1);
        }
    }

    u64* zo = g_zend + ((size_t)(b * K + k) * NP) * H + h;
#pragma unroll
    for (int j = 0; j < NP; ++j) zo[(size_t)j * H] = z[j];
}

// ------------------------------------------------------------------ carry
// warp = (b, hw, j); lane = h_local. Sequential prefix over chunks:
// S_k = q * S_{k-1} + zend_{k-1}
__global__ __launch_bounds__(128, 8)
void s4_carry()
{
    const int warp = blockIdx.x * 4 + (threadIdx.x >> 5);
    const int lane = threadIdx.x & 31;
    const int j  = warp & (NP - 1);
    const int hw = (warp >> 5) & 15;
    const int b  = warp >> 9;
    const int h  = hw * 32 + lane;

    const u64 q = g_q2[j * H + h];
    u64 S = 0ull;
    u64 znext = g_zend[((size_t)(b * K + 0) * NP + j) * H + h];
    for (int k = 1; k < K; ++k) {
        const u64 zc = znext;
        if (k + 1 < K)
            znext = g_zend[((size_t)(b * K + k) * NP + j) * H + h];
        S = fma2_(q, S, zc);
        g_S[((size_t)(b * K + k) * NP + j) * H + h] = S;
    }
}

// ------------------------------------------------------------------ fix
// warp = (b, hw, k>=1). Adds y(kT + i) += sum_n c_n a_n^{i+1} S_{k,n}.
__global__ __launch_bounds__(128, 2)
void s4_fix(float* __restrict__ y)
{
    const int warp = blockIdx.x * 4 + (threadIdx.x >> 5);
    const int lane = threadIdx.x & 31;
    const int k  = 1 + (warp % (K - 1));
    const int hw = (warp / (K - 1)) & 15;
    const int b  = warp / ((K - 1) * 16);
    const int h  = hw * 32 + lane;

    u64 a[NP], c[NP], g[NP];
#pragma unroll
    for (int j = 0; j < NP; ++j) {
        a[j] = g_a2[j * H + h];
        c[j] = g_c2[j * H + h];
        g[j] = mul2_(a[j], g_S[((size_t)(b * K + k) * NP + j) * H + h]);
    }

    float* yb = y + ((size_t)b * SEQLEN + (size_t)k * TCH) * H + h;

    float yp0 = yb[0 * H], yp1 = yb[1 * H], yp2 = yb[2 * H], yp3 = yb[3 * H];

    for (int t = 0; t < TCH; t += 4) {
        float yv[4] = {yp0, yp1, yp2, yp3};
        if (t + 4 < TCH) {
            const float* p = yb + (size_t)(t + 4) * H;
            yp0 = p[0 * H]; yp1 = p[1 * H]; yp2 = p[2 * H]; yp3 = p[3 * H];
        }
#pragma unroll
        for (int s = 0; s < 4; ++s) {
            u64 ac0 = 0ull, ac1 = 0ull, ac2 = 0ull, ac3 = 0ull;
#pragma unroll
            for (int j = 0; j < NP; j += 4) {
                ac0 = fma2_(c[j + 0], g[j + 0], ac0); g[j + 0] = mul2_(a[j + 0], g[j + 0]);
                ac1 = fma2_(c[j + 1], g[j + 1], ac1); g[j + 1] = mul2_(a[j + 1], g[j + 1]);
                ac2 = fma2_(c[j + 2], g[j + 2], ac2); g[j + 2] = mul2_(a[j + 2], g[j + 2]);
                ac3 = fma2_(c[j + 3], g[j + 3], ac3); g[j + 3] = mul2_(a[j + 3], g[j + 3]);
            }
            const u64 sA = add2_(ac0, ac1);
            const u64 sB = add2_(ac2, ac3);
            const u64 sS = add2_(sA, sB);
            float x0, x1; unpack2(sS, x0, x1);
            yb[(size_t)(t + s) * H] = yv[s] + (x0 + x1);
        }
    }
}

extern "C" void kernel_launch(void* const* d_in, const int* in_sizes, int n_in,
                              void* d_out, int out_size)
{
    const float* u      = (const float*)d_in[0];
    const float* B_re   = (const float*)d_in[1];
    const float* C_re   = (const float*)d_in[2];
    const float* log_dt = (const float*)d_in[3];
    const float* Dp     = (const float*)d_in[4];
    float* y = (float*)d_out;

    s4_precomp<<<(NP * H + 127) / 128, 128>>>(B_re, C_re, log_dt);
    // scan: BATCH*16*K = 1024 warps
    s4_scan<<<(BATCH * 16 * K) / 4, 128>>>(u, Dp, y);
    // carry: BATCH*16*NP = 1024 warps
    s4_carry<<<(BATCH * 16 * NP) / 4, 128>>>();
    // fix: BATCH*16*(K-1) = 992 warps
    s4_fix<<<(BATCH * 16 * (K - 1)) / 4, 128>>>(y);
}

// round 4
// speedup vs baseline: 2.6025x; 1.1925x over previous
#include <cuda_runtime.h>
#include <math.h>

#define BATCH  2
#define SEQLEN 2048
#define H      512
#define NST    64
#define NP     32          // state pairs per channel
#define K      32          // time chunks
#define TCH    64          // SEQLEN / K

typedef unsigned long long u64;

// coefficient tables, pair-packed, [pair j][h] layout (coalesced over h)
__device__ u64 g_a2[NP * H];
__device__ u64 g_c2[NP * H];
__device__ u64 g_q2[NP * H];
// end-of-chunk local states and chunk-entry carries: [b][k][j][h]
__device__ u64 g_zend[BATCH * K * NP * H];
__device__ u64 g_S[BATCH * K * NP * H];

__device__ __forceinline__ u64 pack2(float lo, float hi) {
    u64 r; asm("mov.b64 %0, {%1, %2};" : "=l"(r) : "f"(lo), "f"(hi)); return r;
}
__device__ __forceinline__ void unpack2(u64 v, float& lo, float& hi) {
    asm("mov.b64 {%0, %1}, %2;" : "=f"(lo), "=f"(hi) : "l"(v));
}
__device__ __forceinline__ u64 fma2_(u64 a, u64 b, u64 c) {
    u64 d; asm("fma.rn.f32x2 %0, %1, %2, %3;" : "=l"(d) : "l"(a), "l"(b), "l"(c)); return d;
}
__device__ __forceinline__ u64 add2_(u64 a, u64 b) {
    u64 d; asm("add.rn.f32x2 %0, %1, %2;" : "=l"(d) : "l"(a), "l"(b)); return d;
}

// ---------------------------------------------------------------- precompute
__global__ void s4_precomp(const float* __restrict__ B_re,
                           const float* __restrict__ C_re,
                           const float* __restrict__ log_dt)
{
    const int idx = blockIdx.x * blockDim.x + threadIdx.x;   // (j, h)
    if (idx >= NP * H) return;
    const int h = idx % H;
    const int j = idx / H;
    const float delta = expf(log_dt[h]);
    float av[2], cv[2], qv[2];
#pragma unroll
    for (int s = 0; s < 2; ++s) {
        const int n = 2 * j + s;
        const float A  = rsqrtf(1.0f + (float)(n + 1) * (1.0f / NST));
        const float dA = delta * A;
        av[s] = expf(dA);
        cv[s] = expm1f(dA) * B_re[n] * delta * C_re[n];
        qv[s] = expf(dA * (float)TCH);
    }
    g_a2[idx] = pack2(av[0], av[1]);
    g_c2[idx] = pack2(cv[0], cv[1]);
    g_q2[idx] = pack2(qv[0], qv[1]);
}

// ------------------------------------------------------------------ pass 1
// State-only local scan per (b, hw, k): z = a*z + u, write zend. No y.
__global__ __launch_bounds__(128, 3)
void s4_pass1(const float* __restrict__ u)
{
    const int warp = blockIdx.x * 4 + (threadIdx.x >> 5);
    const int lane = threadIdx.x & 31;
    const int k  = warp & (K - 1);
    const int hw = (warp >> 5) & 15;
    const int b  = warp >> 9;
    const int h  = hw * 32 + lane;

    u64 a[NP], z[NP];
#pragma unroll
    for (int j = 0; j < NP; ++j) {
        a[j] = g_a2[j * H + h];
        z[j] = 0ull;
    }

    const float* ub = u + ((size_t)b * SEQLEN + (size_t)k * TCH) * H + h;

    float up[8];
#pragma unroll
    for (int s = 0; s < 8; ++s) up[s] = ub[(size_t)s * H];

    for (int t = 0; t < TCH; t += 8) {
        float uc[8];
#pragma unroll
        for (int s = 0; s < 8; ++s) uc[s] = up[s];
        if (t + 8 < TCH) {
            const float* p = ub + (size_t)(t + 8) * H;
#pragma unroll
            for (int s = 0; s < 8; ++s) up[s] = p[(size_t)s * H];
        }
#pragma unroll
        for (int s = 0; s < 8; ++s) {
            const u64 ubb = pack2(uc[s], uc[s]);
#pragma unroll
            for (int j = 0; j < NP; ++j)
                z[j] = fma2_(a[j], z[j], ubb);
        }
    }

    u64* zo = g_zend + ((size_t)(b * K + k) * NP) * H + h;
#pragma unroll
    for (int j = 0; j < NP; ++j) zo[(size_t)j * H] = z[j];
}

// ------------------------------------------------------------------ carry
// warp = (b, hw, j); lane = h_local. Prefix over chunks: S_k = q S_{k-1} + zend_{k-1}
__global__ __launch_bounds__(128, 8)
void s4_carry()
{
    const int warp = blockIdx.x * 4 + (threadIdx.x >> 5);
    const int lane = threadIdx.x & 31;
    const int j  = warp & (NP - 1);
    const int hw = (warp >> 5) & 15;
    const int b  = warp >> 9;
    const int h  = hw * 32 + lane;

    const u64 q = g_q2[j * H + h];
    u64 S = 0ull;
    u64 znext = g_zend[((size_t)(b * K + 0) * NP + j) * H + h];
    for (int k = 1; k < K; ++k) {
        const u64 zc = znext;
        if (k + 1 < K)
            znext = g_zend[((size_t)(b * K + k) * NP + j) * H + h];
        S = fma2_(q, S, zc);
        g_S[((size_t)(b * K + k) * NP + j) * H + h] = S;
    }
}

// ------------------------------------------------------------------ pass 2
// Full scan seeded with the true chunk-entry state; writes y exactly once.
__global__ __launch_bounds__(128, 2)
void s4_pass2(const float* __restrict__ u,
              const float* __restrict__ Dp,
              float* __restrict__ y)
{
    const int warp = blockIdx.x * 4 + (threadIdx.x >> 5);
    const int lane = threadIdx.x & 31;
    const int k  = warp & (K - 1);
    const int hw = (warp >> 5) & 15;
    const int b  = warp >> 9;
    const int h  = hw * 32 + lane;

    u64 a[NP], c[NP], z[NP];
#pragma unroll
    for (int j = 0; j < NP; ++j) {
        a[j] = g_a2[j * H + h];
        c[j] = g_c2[j * H + h];
    }
    if (k > 0) {
        const u64* Sp = g_S + ((size_t)(b * K + k) * NP) * H + h;
#pragma unroll
        for (int j = 0; j < NP; ++j) z[j] = Sp[(size_t)j * H];
    } else {
#pragma unroll
        for (int j = 0; j < NP; ++j) z[j] = 0ull;
    }
    const float Dh = Dp[h];

    const size_t base = ((size_t)b * SEQLEN + (size_t)k * TCH) * H + h;
    const float* ub = u + base;
    float*       yb = y + base;

    float up0 = ub[0 * H], up1 = ub[1 * H], up2 = ub[2 * H], up3 = ub[3 * H];

    for (int t = 0; t < TCH; t += 4) {
        float uc[4] = {up0, up1, up2, up3};
        if (t + 4 < TCH) {
            const float* p = ub + (size_t)(t + 4) * H;
            up0 = p[0 * H]; up1 = p[1 * H]; up2 = p[2 * H]; up3 = p[3 * H];
        }
#pragma unroll
        for (int s = 0; s < 4; ++s) {
            const float ut = uc[s];
            const u64 ubb = pack2(ut, ut);
            u64 ac0 = 0ull, ac1 = 0ull, ac2 = 0ull, ac3 = 0ull;
#pragma unroll
            for (int j = 0; j < NP; j += 4) {
                z[j + 0] = fma2_(a[j + 0], z[j + 0], ubb); ac0 = fma2_(c[j + 0], z[j + 0], ac0);
                z[j + 1] = fma2_(a[j + 1], z[j + 1], ubb); ac1 = fma2_(c[j + 1], z[j + 1], ac1);
                z[j + 2] = fma2_(a[j + 2], z[j + 2], ubb); ac2 = fma2_(c[j + 2], z[j + 2], ac2);
                z[j + 3] = fma2_(a[j + 3], z[j + 3], ubb); ac3 = fma2_(c[j + 3], z[j + 3], ac3);
            }
            const u64 sA = add2_(ac0, ac1);
            const u64 sB = add2_(ac2, ac3);
            const u64 sS = add2_(sA, sB);
            float x0, x1; unpack2(sS, x0, x1);
            yb[(size_t)(t + s) * H] = fmaf(Dh, ut, x0 + x1);
        }
    }
}

extern "C" void kernel_launch(void* const* d_in, const int* in_sizes, int n_in,
                              void* d_out, int out_size)
{
    const float* u      = (const float*)d_in[0];
    const float* B_re   = (const float*)d_in[1];
    const float* C_re   = (const float*)d_in[2];
    const float* log_dt = (const float*)d_in[3];
    const float* Dp     = (const float*)d_in[4];
    float* y = (float*)d_out;

    s4_precomp<<<(NP * H + 127) / 128, 128>>>(B_re, C_re, log_dt);
    s4_pass1<<<(BATCH * 16 * K) / 4, 128>>>(u);
    s4_carry<<<(BATCH * 16 * NP) / 4, 128>>>();
    s4_pass2<<<(BATCH * 16 * K) / 4, 128>>>(u, Dp, y);
}

// round 5
// speedup vs baseline: 2.7508x; 1.0570x over previous
#include <cuda_runtime.h>
#include <math.h>

#define BATCH  2
#define SEQLEN 2048
#define H      512
#define NST    64
#define NP     32          // state pairs per channel
#define NPH    16          // state pairs per warp (pair-split)
#define K      32          // time chunks
#define TCH    64          // SEQLEN / K
#define TT     8           // timesteps per smem tile in pass2
#define NTIL   (TCH / TT)  // 8

typedef unsigned long long u64;

// coefficient tables, pair-packed, [pair j][h] layout (coalesced over h)
__device__ u64 g_a2[NP * H];
__device__ u64 g_c2[NP * H];
__device__ u64 g_q2[NP * H];
// end-of-chunk local states and chunk-entry carries: [b][k][j][h]
__device__ u64 g_zend[BATCH * K * NP * H];
__device__ u64 g_S[BATCH * K * NP * H];

__device__ __forceinline__ u64 pack2(float lo, float hi) {
    u64 r; asm("mov.b64 %0, {%1, %2};" : "=l"(r) : "f"(lo), "f"(hi)); return r;
}
__device__ __forceinline__ void unpack2(u64 v, float& lo, float& hi) {
    asm("mov.b64 {%0, %1}, %2;" : "=f"(lo), "=f"(hi) : "l"(v));
}
__device__ __forceinline__ u64 fma2_(u64 a, u64 b, u64 c) {
    u64 d; asm("fma.rn.f32x2 %0, %1, %2, %3;" : "=l"(d) : "l"(a), "l"(b), "l"(c)); return d;
}
__device__ __forceinline__ u64 add2_(u64 a, u64 b) {
    u64 d; asm("add.rn.f32x2 %0, %1, %2;" : "=l"(d) : "l"(a), "l"(b)); return d;
}

// ---------------------------------------------------------------- precompute
__global__ void s4_precomp(const float* __restrict__ B_re,
                           const float* __restrict__ C_re,
                           const float* __restrict__ log_dt)
{
    const int idx = blockIdx.x * blockDim.x + threadIdx.x;   // (j, h)
    if (idx >= NP * H) return;
    const int h = idx % H;
    const int j = idx / H;
    const float delta = expf(log_dt[h]);
    float av[2], cv[2], qv[2];
#pragma unroll
    for (int s = 0; s < 2; ++s) {
        const int n = 2 * j + s;
        const float A  = rsqrtf(1.0f + (float)(n + 1) * (1.0f / NST));
        const float dA = delta * A;
        av[s] = expf(dA);
        cv[s] = expm1f(dA) * B_re[n] * delta * C_re[n];
        qv[s] = expf(dA * (float)TCH);
    }
    g_a2[idx] = pack2(av[0], av[1]);
    g_c2[idx] = pack2(cv[0], cv[1]);
    g_q2[idx] = pack2(qv[0], qv[1]);
}

// ------------------------------------------------------------------ pass 1
// State-only local scan. Warp-pair split: global warp gw -> pair gp = gw>>1,
// half = gw&1 owns state-pairs [half*16, half*16+16). No smem needed.
__global__ __launch_bounds__(128, 4)
void s4_pass1(const float* __restrict__ u)
{
    const int w    = threadIdx.x >> 5;
    const int lane = threadIdx.x & 31;
    const int gw   = blockIdx.x * 4 + w;      // 2048 warps
    const int half = gw & 1;
    const int gp   = gw >> 1;                 // 1024 chunk-pairs
    const int k  = gp & (K - 1);
    const int hw = (gp >> 5) & 15;
    const int b  = gp >> 9;
    const int h  = hw * 32 + lane;
    const int jb = half * NPH;

    u64 a[NPH], z[NPH];
#pragma unroll
    for (int j = 0; j < NPH; ++j) {
        a[j] = g_a2[(jb + j) * H + h];
        z[j] = 0ull;
    }

    const float* ub = u + ((size_t)b * SEQLEN + (size_t)k * TCH) * H + h;

    float up[8];
#pragma unroll
    for (int s = 0; s < 8; ++s) up[s] = ub[(size_t)s * H];

    for (int t = 0; t < TCH; t += 8) {
        float uc[8];
#pragma unroll
        for (int s = 0; s < 8; ++s) uc[s] = up[s];
        if (t + 8 < TCH) {
            const float* p = ub + (size_t)(t + 8) * H;
#pragma unroll
            for (int s = 0; s < 8; ++s) up[s] = p[(size_t)s * H];
        }
#pragma unroll
        for (int s = 0; s < 8; ++s) {
            const u64 ubb = pack2(uc[s], uc[s]);
#pragma unroll
            for (int j = 0; j < NPH; ++j)
                z[j] = fma2_(a[j], z[j], ubb);
        }
    }

    u64* zo = g_zend + ((size_t)(b * K + k) * NP + jb) * H + h;
#pragma unroll
    for (int j = 0; j < NPH; ++j) zo[(size_t)j * H] = z[j];
}

// ------------------------------------------------------------------ carry
// Prefix over chunks: S_k = q S_{k-1} + zend_{k-1}. All zend prefetched
// up-front (MLP=31) so the loop is a pure fma chain.
__global__ __launch_bounds__(128, 4)
void s4_carry()
{
    const int w    = threadIdx.x >> 5;
    const int lane = threadIdx.x & 31;
    const int gw   = blockIdx.x * 4 + w;      // 1024 warps
    const int j  = gw & (NP - 1);
    const int hw = (gw >> 5) & 15;
    const int b  = gw >> 9;
    const int h  = hw * 32 + lane;

    const u64 q = g_q2[j * H + h];
    const u64* zp = g_zend + ((size_t)(b * K) * NP + j) * H + h;
    u64 zz[K - 1];
#pragma unroll
    for (int k = 0; k < K - 1; ++k) zz[k] = zp[(size_t)k * NP * H];

    u64* Sp = g_S + ((size_t)(b * K) * NP + j) * H + h;
    u64 S = 0ull;
#pragma unroll
    for (int k = 1; k < K; ++k) {
        S = fma2_(q, S, zz[k - 1]);
        Sp[(size_t)k * NP * H] = S;
    }
}

// ------------------------------------------------------------------ pass 2
// Warp-pair split full scan, seeded with true chunk-entry state.
// Block = 128 threads = 2 pairs. Each half computes a 16-pair partial dot;
// partials combined via smem with one __syncthreads per 8-timestep tile.
// half==1 additionally stages u tiles into smem (loaded once per pair).
__global__ __launch_bounds__(128, 4)
void s4_pass2(const float* __restrict__ u,
              const float* __restrict__ Dp,
              float* __restrict__ y)
{
    __shared__ float su[2][2][TT][32];        // [pair][buf][t][lane]
    __shared__ float sp[2][2][TT][2][32];     // [pair][buf][t][half][lane]

    const int w    = threadIdx.x >> 5;
    const int lane = threadIdx.x & 31;
    const int pair = w >> 1;
    const int half = w & 1;
    const int gp   = blockIdx.x * 2 + pair;   // 1024 chunk-pairs
    const int k  = gp & (K - 1);
    const int hw = (gp >> 5) & 15;
    const int b  = gp >> 9;
    const int h  = hw * 32 + lane;
    const int jb = half * NPH;

    u64 a[NPH], c[NPH], z[NPH];
#pragma unroll
    for (int j = 0; j < NPH; ++j) {
        a[j] = g_a2[(jb + j) * H + h];
        c[j] = g_c2[(jb + j) * H + h];
    }
    if (k > 0) {
        const u64* Sp = g_S + ((size_t)(b * K + k) * NP + jb) * H + h;
#pragma unroll
        for (int j = 0; j < NPH; ++j) z[j] = Sp[(size_t)j * H];
    } else {
#pragma unroll
        for (int j = 0; j < NPH; ++j) z[j] = 0ull;
    }
    const float Dh = Dp[h];

    const size_t base = ((size_t)b * SEQLEN + (size_t)k * TCH) * H + h;
    const float* ub = u + base;
    float*       yb = y + base;

    // stage u tile 0
    if (half == 1) {
#pragma unroll
        for (int s = 0; s < TT; ++s) su[pair][0][s][lane] = ub[(size_t)s * H];
    }
    __syncthreads();

    float uc[TT];

    for (int i = 0; i < NTIL; ++i) {
        const int buf = i & 1;

        // half==1 prefetches next u tile into the other buffer
        if (half == 1 && i + 1 < NTIL) {
            const float* pn = ub + (size_t)(i + 1) * TT * H;
#pragma unroll
            for (int s = 0; s < TT; ++s) su[pair][buf ^ 1][s][lane] = pn[(size_t)s * H];
        }

#pragma unroll
        for (int s = 0; s < TT; ++s) {
            const float ut = su[pair][buf][s][lane];
            uc[s] = ut;
            const u64 ubb = pack2(ut, ut);
            u64 ac0 = 0ull, ac1 = 0ull;
#pragma unroll
            for (int j = 0; j < NPH; j += 2) {
                z[j]     = fma2_(a[j],     z[j],     ubb); ac0 = fma2_(c[j],     z[j],     ac0);
                z[j + 1] = fma2_(a[j + 1], z[j + 1], ubb); ac1 = fma2_(c[j + 1], z[j + 1], ac1);
            }
            const u64 sS = add2_(ac0, ac1);
            float x0, x1; unpack2(sS, x0, x1);
            sp[pair][buf][s][half][lane] = x0 + x1;
        }

        __syncthreads();

        if (half == 0) {
#pragma unroll
            for (int s = 0; s < TT; ++s) {
                const float p0 = sp[pair][buf][s][0][lane];
                const float p1 = sp[pair][buf][s][1][lane];
                yb[(size_t)(i * TT + s) * H] = fmaf(Dh, uc[s], p0 + p1);
            }
        }
    }
}

extern "C" void kernel_launch(void* const* d_in, const int* in_sizes, int n_in,
                              void* d_out, int out_size)
{
    const float* u      = (const float*)d_in[0];
    const float* B_re   = (const float*)d_in[1];
    const float* C_re   = (const float*)d_in[2];
    const float* log_dt = (const float*)d_in[3];
    const float* Dp     = (const float*)d_in[4];
    float* y = (float*)d_out;

    s4_precomp<<<(NP * H + 127) / 128, 128>>>(B_re, C_re, log_dt);
    // pass1: 2048 warps (pair-split), 512 blocks
    s4_pass1<<<(BATCH * 16 * K * 2) / 4, 128>>>(u);
    // carry: 1024 warps, 256 blocks
    s4_carry<<<(BATCH * 16 * NP) / 4, 128>>>();
    // pass2: 1024 chunk-pairs = 2048 warps, 512 blocks
    s4_pass2<<<(BATCH * 16 * K) / 2, 128>>>(u, Dp, y);
}